// round 16
// baseline (speedup 1.0000x reference)
#include <cuda_runtime.h>
#include <cuda_bf16.h>
#include <mma.h>
#include <cstdint>
#include <math.h>

#define V_SZ 100000
#define H_SZ 300
#define HP   304
#define B_SZ 64
#define L_SZ 64
#define ENC_GRID 150       // 2 n-rows per block
#define NT   1564          // tiles of 64 rows: 1564*64 = 100096 >= V_SZ
#define NB_MMA 782         // k_mma blocks: 2 tiles each
#define KT   304           // MMA K padded: 19 k16-steps
#define CAP  16384
#define AT_BYTES (64 * KT * 2)        // 38912 per 64-row tile
#define B_BYTES  (B_SZ * KT * 2)      // 38912 (h^T tile)
#define BIAS_OFF (2 * AT_BYTES + B_BYTES)  // 116736
#define DSMEM_SZ (BIAS_OFF + 512)          // 117248 -> 1 block/SM, pipelined

typedef unsigned long long ull;
using namespace nvcuda;

// ---------------- device scratch ----------------
__device__ __align__(16) float g_h[2][HP * B_SZ];
__device__ __align__(16) float g_xT[HP * B_SZ];
__device__ __align__(16) float g_xT_all[L_SZ * HP * B_SZ];
__device__ __align__(16) unsigned char g_Wb[(size_t)NT * AT_BYTES];   // bf16 tiles
__device__ __align__(16) unsigned char g_hb[B_BYTES];                 // bf16 h^T
__device__ __align__(16) unsigned char g_approx[(size_t)NT * 64 * B_SZ * 2]; // bf16
__device__ ull g_gmax[B_SZ];
__device__ float g_l1[B_SZ];
__device__ int g_ccnt[B_SZ];
__device__ int g_cand[(size_t)B_SZ * CAP];
__device__ unsigned g_bar;

// ---------------- helpers ----------------
static __device__ __forceinline__ ull pk2(float lo, float hi) {
    ull r; asm("mov.b64 %0, {%1, %2};" : "=l"(r) : "f"(lo), "f"(hi)); return r;
}
static __device__ __forceinline__ void ffma2(ull& d, ull a, ull b) {
    asm("fma.rn.f32x2 %0, %1, %2, %0;" : "+l"(d) : "l"(a), "l"(b));
}
static __device__ __forceinline__ float2 upk2(ull v) {
    float2 r; asm("mov.b64 {%0, %1}, %2;" : "=f"(r.x), "=f"(r.y) : "l"(v)); return r;
}
static __device__ __forceinline__ unsigned ordf(float f) {
    unsigned u = __float_as_uint(f);
    return (u & 0x80000000u) ? ~u : (u | 0x80000000u);
}
static __device__ __forceinline__ float unordf(unsigned u) {
    return __uint_as_float((u & 0x80000000u) ? (u ^ 0x80000000u) : ~u);
}
static __device__ __forceinline__ ull umax64(ull a, ull b) { return a > b ? a : b; }
static __device__ __forceinline__ unsigned s2u(const void* p) {
    return (unsigned)__cvta_generic_to_shared(p);
}
static __device__ __forceinline__ unsigned pbf2(float lo, float hi) {
    unsigned r;
    asm("cvt.rn.bf16x2.f32 %0, %1, %2;" : "=r"(r) : "f"(hi), "f"(lo));
    return r;
}
#define CP16(dst, src) asm volatile("cp.async.cg.shared.global [%0], [%1], 16;" :: "r"(dst), "l"(src))
#define MARGIN_OF(l1) (3.0e-4f * (l1) + 1.5e-3f)

// ---------------- cheap double transcendentals ----------------
static __device__ __forceinline__ double dexp_(double x) {
    const double L2E = 1.4426950408889634074;
    const double LN2HI = 6.93147180369123816490e-01;
    const double LN2LO = 1.90821492927058770002e-10;
    int n = __double2int_rn(x * L2E);
    double nd = (double)n;
    double r = fma(-nd, LN2HI, x);
    r = fma(-nd, LN2LO, r);
    double p = 2.7557319223985893e-6;
    p = fma(p, r, 2.4801587301587302e-5);
    p = fma(p, r, 1.9841269841269841e-4);
    p = fma(p, r, 1.3888888888888889e-3);
    p = fma(p, r, 8.3333333333333333e-3);
    p = fma(p, r, 4.1666666666666667e-2);
    p = fma(p, r, 1.6666666666666667e-1);
    p = fma(p, r, 0.5);
    p = fma(p, r, 1.0);
    p = fma(p, r, 1.0);
    return p * __longlong_as_double((long long)((ull)(1023 + n) << 52));
}
static __device__ __forceinline__ float sigd(float x) {
    double xd = (double)fminf(fmaxf(x, -30.0f), 30.0f);
    double e = dexp_(-xd);
    double den = 1.0 + e;
    double r0 = (double)(1.0f / (float)den);
    r0 = r0 * fma(-den, r0, 2.0);
    return (float)r0;
}
static __device__ __forceinline__ float tanhd(float x) {
    double xd = (double)fminf(fmaxf(x, -30.0f), 30.0f);
    double e = dexp_(-2.0 * xd);
    double den = 1.0 + e;
    double r0 = (double)(1.0f / (float)den);
    r0 = r0 * fma(-den, r0, 2.0);
    return (float)fma(-2.0 * e, r0, 1.0);
}

// ---------------- init ----------------
__global__ void k_init(const float* __restrict__ emb) {
    int i = blockIdx.x * 256 + threadIdx.x;    // 76*256 = HP*64 exact
    int k = i >> 6;
    g_h[0][i] = 0.0f;
    g_h[1][i] = 0.0f;
    g_xT[i] = (k < H_SZ) ? fmaxf(emb[k], 0.0f) : 0.0f;
    if (i == 0) g_bar = 0u;
    if (i < 64) { g_gmax[i] = 0ull; g_l1[i] = 0.f; g_ccnt[i] = 0; }
    if (i < 128) {            // zero g_hb pads (cols 300..303, 64 rows)
        int b = i >> 1, pr = i & 1;
        ((unsigned*)g_hb)[(b * KT + 300) / 2 + pr] = 0u;
    }
}

// ---------------- prep: W -> bf16 row-major tiles [64][KT] ---------------
__global__ __launch_bounds__(256) void k_prep(const float* __restrict__ W) {
    int blk = blockIdx.x, tid = threadIdx.x;
    unsigned* dst = (unsigned*)(g_Wb + (size_t)blk * AT_BYTES);
    for (int i = tid; i < 64 * (KT / 2); i += 256) {
        int l = i / (KT / 2), kw = i - l * (KT / 2);
        int k0 = kw * 2;
        int row = blk * 64 + l;
        float v0 = 0.f, v1 = 0.f;
        if (row < V_SZ) {
            if (k0 < H_SZ)     v0 = W[(size_t)row * H_SZ + k0];
            if (k0 + 1 < H_SZ) v1 = W[(size_t)row * H_SZ + k0 + 1];
        }
        dst[i] = pbf2(v0, v1);
    }
}

// ---------------- gather encoder embeddings ----------------
__global__ void k_gather_enc(const int* __restrict__ input, const float* __restrict__ emb) {
    __shared__ int ids[B_SZ];
    int t = blockIdx.x, tid = threadIdx.x;
    if (tid < B_SZ) ids[tid] = input[t * B_SZ + tid];
    __syncthreads();
    for (int i = tid; i < B_SZ * H_SZ; i += 256) {
        int b = i / H_SZ, k = i - b * H_SZ;
        g_xT_all[((size_t)t * HP + k) * B_SZ + b] = emb[(size_t)ids[b] * H_SZ + k];
    }
    g_xT_all[((size_t)t * HP + H_SZ) * B_SZ + tid] = 0.0f;
}

// ---------------- encoder: persistent, grid 150 (2 n-rows/block) ---------
// Row layout: r in 0..5 = W_ih gate (r>>1), local row (r&1); r in 6..11 = W_hh.
__global__ __launch_bounds__(512, 2) void k_enc_all(
    const float* __restrict__ W_ih, const float* __restrict__ W_hh,
    const float* __restrict__ b_ih, const float* __restrict__ b_hh)
{
    __shared__ __align__(16) float Ws[12][HP];       // 14592 B, persists
    __shared__ __align__(16) ull Red[8 * 12 * 32];   // 24576 B

    int tid = threadIdx.x;
    int n0 = blockIdx.x * 2;
    int w = tid >> 5, lane = tid & 31;

    for (int i = tid; i < 12 * 75; i += 512) {
        int row = i / 75, q = i - row * 75;
        const float* src;
        if (row < 6) src = W_ih + (size_t)((row >> 1) * H_SZ + n0 + (row & 1)) * H_SZ;
        else { int rr = row - 6; src = W_hh + (size_t)((rr >> 1) * H_SZ + n0 + (rr & 1)) * H_SZ; }
        *(float4*)&Ws[row][q * 4] = *(const float4*)(src + q * 4);
    }
    if (tid < 12) { float4 z = {0.f, 0.f, 0.f, 0.f}; *(float4*)&Ws[tid][300] = z; }

    float bi_r = 0, bi_z = 0, bi_n = 0, bh_r = 0, bh_z = 0, bh_n = 0;
    int nl = 0, bb = 0, nn_i = 0;
    if (tid < 128) {
        nl = tid >> 6; bb = tid & 63; nn_i = n0 + nl;
        bi_r = b_ih[nn_i]; bi_z = b_ih[H_SZ + nn_i]; bi_n = b_ih[2 * H_SZ + nn_i];
        bh_r = b_hh[nn_i]; bh_z = b_hh[H_SZ + nn_i]; bh_n = b_hh[2 * H_SZ + nn_i];
    }
    __syncthreads();

    int ks = w * 19;
    for (int t = 0; t < L_SZ; t++) {
        const float* xp = g_xT_all + (size_t)t * HP * B_SZ;
        const float* hp = g_h[t & 1];
        float* ho = g_h[(t + 1) & 1];

        ull a[12];
#pragma unroll
        for (int r = 0; r < 12; r++) a[r] = 0ull;

#pragma unroll 4
        for (int k = ks; k < ks + 19; k++) {
            ull xq = *(const ull*)(xp + k * 64 + lane * 2);
            ull hq = *(const ull*)(hp + k * 64 + lane * 2);
#pragma unroll
            for (int r = 0; r < 6; r++) ffma2(a[r], pk2(Ws[r][k], Ws[r][k]), xq);
#pragma unroll
            for (int r = 6; r < 12; r++) ffma2(a[r], pk2(Ws[r][k], Ws[r][k]), hq);
        }

        if (w >= 8) {
#pragma unroll
            for (int r = 0; r < 12; r++) Red[((w - 8) * 12 + r) * 32 + lane] = a[r];
        }
        __syncthreads();
        if (w < 8) {
#pragma unroll
            for (int r = 0; r < 12; r++) {
                ull o = Red[(w * 12 + r) * 32 + lane];
                float2 pa = upk2(a[r]), po = upk2(o);
                Red[(w * 12 + r) * 32 + lane] = pk2(pa.x + po.x, pa.y + po.y);
            }
        }
        __syncthreads();
        if (tid < 128) {
            const float* Rf = (const float*)Red;   // [8][12][64]
            float sir = 0, siz = 0, sin_ = 0, shr = 0, shz = 0, shn = 0;
#pragma unroll
            for (int p2 = 0; p2 < 8; p2++) {
                const float* base = Rf + p2 * 768;
                sir  += base[(0 + nl) * 64 + bb];
                siz  += base[(2 + nl) * 64 + bb];
                sin_ += base[(4 + nl) * 64 + bb];
                shr  += base[(6 + nl) * 64 + bb];
                shz  += base[(8 + nl) * 64 + bb];
                shn  += base[(10 + nl) * 64 + bb];
            }
            float r = sigd(sir + bi_r + shr + bh_r);
            float z = sigd(siz + bi_z + shz + bh_z);
            float nn = tanhd(sin_ + bi_n + r * (shn + bh_n));
            float hold = hp[nn_i * 64 + bb];
            ho[nn_i * 64 + bb] = (1.0f - z) * nn + z * hold;
            __threadfence();
        }
        __syncthreads();
        if (tid == 0) {
            atomicAdd(&g_bar, 1u);
            unsigned target = (unsigned)(t + 1) * (unsigned)ENC_GRID;
            unsigned v;
            do {
                asm volatile("ld.acquire.gpu.u32 %0, [%1];" : "=r"(v) : "l"(&g_bar));
            } while (v < target);
        }
        __syncthreads();
    }
}

// ---------------- decoder GRU: grid 300 (1 n/block), block 512 -----------
__global__ __launch_bounds__(512) void k_gru(
    const float* __restrict__ W_ih, const float* __restrict__ W_hh,
    const float* __restrict__ b_ih, const float* __restrict__ b_hh,
    int hin, int hout)
{
    __shared__ __align__(16) char smraw[12288];
    float (*Ws)[HP] = (float(*)[HP])smraw;    // [6][304] during main loop
    ull* Red = (ull*)smraw;                   // [8][6][32] after (union)

    int tid = threadIdx.x;
    int n = blockIdx.x;
    int w = tid >> 5, lane = tid & 31;

    for (int i = tid; i < 6 * 75; i += 512) {
        int row = i / 75, q = i - row * 75;
        const float* src = ((row < 3) ? W_ih + (size_t)(row * H_SZ + n) * H_SZ
                                      : W_hh + (size_t)((row - 3) * H_SZ + n) * H_SZ);
        *(float4*)&Ws[row][q * 4] = *(const float4*)(src + q * 4);
    }
    if (tid < 6) { float4 z = {0.f, 0.f, 0.f, 0.f}; *(float4*)&Ws[tid][300] = z; }
    __syncthreads();

    const float* xp = g_xT;
    const float* hp = g_h[hin];
    int ks = w * 19;

    ull a[6];
#pragma unroll
    for (int r = 0; r < 6; r++) a[r] = 0ull;

#pragma unroll 4
    for (int k = ks; k < ks + 19; k++) {
        ull xq = *(const ull*)(xp + k * 64 + lane * 2);
        ull hq = *(const ull*)(hp + k * 64 + lane * 2);
#pragma unroll
        for (int r = 0; r < 3; r++) ffma2(a[r], pk2(Ws[r][k], Ws[r][k]), xq);
#pragma unroll
        for (int r = 3; r < 6; r++) ffma2(a[r], pk2(Ws[r][k], Ws[r][k]), hq);
    }
    __syncthreads();

    if (w >= 8) {
#pragma unroll
        for (int r = 0; r < 6; r++) Red[((w - 8) * 6 + r) * 32 + lane] = a[r];
    }
    __syncthreads();
    if (w < 8) {
#pragma unroll
        for (int r = 0; r < 6; r++) {
            ull o = Red[(w * 6 + r) * 32 + lane];
            float2 pa = upk2(a[r]), po = upk2(o);
            Red[(w * 6 + r) * 32 + lane] = pk2(pa.x + po.x, pa.y + po.y);
        }
    }
    __syncthreads();

    if (tid < 64) {
        int b = tid;
        const float* Rf = (const float*)Red;    // [8][6][64]
        float sir = 0, siz = 0, sin_ = 0, shr = 0, shz = 0, shn = 0;
#pragma unroll
        for (int p2 = 0; p2 < 8; p2++) {
            const float* base = Rf + p2 * 384;
            sir  += base[b];
            siz  += base[64 + b];
            sin_ += base[128 + b];
            shr  += base[192 + b];
            shz  += base[256 + b];
            shn  += base[320 + b];
        }
        float r = sigd(sir + b_ih[n] + shr + b_hh[n]);
        float z = sigd(siz + b_ih[H_SZ + n] + shz + b_hh[H_SZ + n]);
        float nn = tanhd(sin_ + b_ih[2 * H_SZ + n] + r * (shn + b_hh[2 * H_SZ + n]));
        float hold = hp[n * 64 + b];
        float hv = (1.0f - z) * nn + z * hold;
        g_h[hout][n * 64 + b] = hv;
        ((__nv_bfloat16*)g_hb)[b * KT + n] = __float2bfloat16(hv);
        atomicAdd(&g_l1[b], fabsf(hv));
    }
}

// ---------------- logits: WMMA bf16, 2 tiles/block, pipelined ------------
// smem: A0 @0; A1 @AT_BYTES; h^T @2*AT_BYTES; bias[128] @BIAS_OFF.
// B staged ONCE per block (halves B traffic); A1 cp.async overlaps tile0 MMA.
__global__ __launch_bounds__(128) void k_mma(const float* __restrict__ bias) {
    extern __shared__ __align__(16) char smx[];
    int tid = threadIdx.x, blk = blockIdx.x;
    int w = tid >> 5;

    unsigned smA0 = s2u(smx), smA1 = smA0 + AT_BYTES, smB = smA0 + 2 * AT_BYTES;
    const unsigned char* srcA0 = g_Wb + (size_t)(blk * 2) * AT_BYTES;
    const unsigned char* srcA1 = srcA0 + AT_BYTES;

    // group 0: B + A0 + bias;  group 1: A1
    for (int i = tid; i < B_BYTES / 16; i += 128) CP16(smB + i * 16, g_hb + i * 16);
    for (int i = tid; i < AT_BYTES / 16; i += 128) CP16(smA0 + i * 16, srcA0 + i * 16);
    {
        int row = blk * 128 + tid;
        ((float*)(smx + BIAS_OFF))[tid] = (row < V_SZ) ? bias[row] : 0.f;
    }
    asm volatile("cp.async.commit_group;");
    for (int i = tid; i < AT_BYTES / 16; i += 128) CP16(smA1 + i * 16, srcA1 + i * 16);
    asm volatile("cp.async.commit_group;");

    const __nv_bfloat16* Bf = (const __nv_bfloat16*)(smx + 2 * AT_BYTES);
    const float* sb = (const float*)(smx + BIAS_OFF);

#pragma unroll
    for (int ti = 0; ti < 2; ti++) {
        if (ti == 0) asm volatile("cp.async.wait_group 1;");
        else         asm volatile("cp.async.wait_group 0;");
        __syncthreads();

        const __nv_bfloat16* Af = (const __nv_bfloat16*)(smx + ti * AT_BYTES);
        wmma::fragment<wmma::accumulator, 16, 16, 16, float> cfr[4];
#pragma unroll
        for (int ni = 0; ni < 4; ni++) wmma::fill_fragment(cfr[ni], 0.0f);

        for (int ks = 0; ks < KT / 16; ks++) {
            wmma::fragment<wmma::matrix_a, 16, 16, 16, __nv_bfloat16, wmma::row_major> af;
            wmma::load_matrix_sync(af, Af + (w * 16) * KT + ks * 16, KT);
#pragma unroll
            for (int ni = 0; ni < 4; ni++) {
                wmma::fragment<wmma::matrix_b, 16, 16, 16, __nv_bfloat16, wmma::col_major> bf;
                wmma::load_matrix_sync(bf, Bf + (ni * 16) * KT + ks * 16, KT);
                wmma::mma_sync(cfr[ni], af, bf, cfr[ni]);
            }
        }
        __syncthreads();

        float* sap = (float*)(smx + ti * AT_BYTES);   // overlay on this tile's A
#pragma unroll
        for (int ni = 0; ni < 4; ni++)
            wmma::store_matrix_sync(sap + (w * 16) * 64 + ni * 16, cfr[ni], 64,
                                    wmma::mem_row_major);
        __syncthreads();

        int tile = blk * 2 + ti;
        unsigned* gdst = (unsigned*)(g_approx + (size_t)tile * 64 * B_SZ * 2);
#pragma unroll
        for (int j = 0; j < 16; j++) {
            int p = j * 128 + tid;                    // 2048 bf16x2 pairs
            int r = p >> 5, bq = p & 31;
            float bb = sb[ti * 64 + r];
            bool ok = (tile * 64 + r) < V_SZ;
            float v0 = ok ? (sap[r * 64 + bq * 2] + bb) : -1e30f;
            float v1 = ok ? (sap[r * 64 + bq * 2 + 1] + bb) : -1e30f;
            sap[r * 64 + bq * 2] = v0;
            sap[r * 64 + bq * 2 + 1] = v1;
            unsigned lo = (unsigned)__bfloat16_as_ushort(__float2bfloat16_ru(v0));
            unsigned hi = (unsigned)__bfloat16_as_ushort(__float2bfloat16_ru(v1));
            gdst[p] = lo | (hi << 16);
        }
        __syncthreads();

        if (tid < 64) {
            ull m = 0;
            for (int r = 0; r < 64; r++) {
                float v = sap[r * 64 + tid];
                m = umax64(m, ((ull)ordf(v) << 32) | (ull)(~(unsigned)(tile * 64 + r)));
            }
            atomicMax(&g_gmax[tid], m);
        }
        __syncthreads();
    }
}

// ---------------- select candidates (thr computed locally) ---------------
__global__ __launch_bounds__(128) void k_select() {
    __shared__ float sthr[64];
    int tid = threadIdx.x, blk = blockIdx.x;
    if (tid < 64)
        sthr[tid] = unordf((unsigned)(g_gmax[tid] >> 32)) - MARGIN_OF(g_l1[tid]);
    __syncthreads();
    const unsigned* ap = (const unsigned*)(g_approx + (size_t)blk * 64 * B_SZ * 2);
    int base_row = blk * 64;
#pragma unroll 4
    for (int j = 0; j < 16; j++) {
        int p = j * 128 + tid;                 // pair: row r, batches 2bq, 2bq+1
        unsigned pv = ap[p];
        int r = p >> 5, bq = p & 31;
        float v0 = __bfloat162float(__ushort_as_bfloat16((unsigned short)(pv & 0xffffu)));
        float v1 = __bfloat162float(__ushort_as_bfloat16((unsigned short)(pv >> 16)));
        int c0 = bq * 2, c1 = bq * 2 + 1;
        if (v0 >= sthr[c0]) {
            int pos = atomicAdd(&g_ccnt[c0], 1);
            if (pos < CAP) g_cand[(size_t)c0 * CAP + pos] = base_row + r;
        }
        if (v1 >= sthr[c1]) {
            int pos = atomicAdd(&g_ccnt[c1], 1);
            if (pos < CAP) g_cand[(size_t)c1 * CAP + pos] = base_row + r;
        }
    }
}

// ---------------- rescore exact + finalize (overflow-safe) ---------------
__global__ __launch_bounds__(256) void k_rescore(
    const float* __restrict__ W, const float* __restrict__ bias,
    const float* __restrict__ emb, float* __restrict__ out, int t, int hin)
{
    __shared__ float hsh[H_SZ];
    __shared__ ull wbest[8];
    __shared__ int sid;
    int b = blockIdx.x, tid = threadIdx.x, wid = tid >> 5, lane = tid & 31;
    for (int k = tid; k < H_SZ; k += 256) hsh[k] = g_h[hin][k * 64 + b];
    if (tid < 8) wbest[tid] = 0ull;
    __syncthreads();
    int n = g_ccnt[b];
    ull best = 0;
    if (n <= CAP) {
        for (int ci = wid; ci < n; ci += 8) {
            int r = g_cand[(size_t)b * CAP + ci];
            const float* wr = W + (size_t)r * H_SZ;
            float s = 0.f;
            for (int k = lane; k < H_SZ; k += 32) s = fmaf(wr[k], hsh[k], s);
#pragma unroll
            for (int o = 16; o; o >>= 1) s += __shfl_xor_sync(0xffffffffu, s, o);
            if (lane == 0) {
                float v = s + bias[r];
                best = umax64(best, ((ull)ordf(v) << 32) | (ull)(~(unsigned)r));
            }
        }
    } else {
        for (int r = wid; r < V_SZ; r += 8) {
            const float* wr = W + (size_t)r * H_SZ;
            float s = 0.f;
            for (int k = lane; k < H_SZ; k += 32) s = fmaf(wr[k], hsh[k], s);
#pragma unroll
            for (int o = 16; o; o >>= 1) s += __shfl_xor_sync(0xffffffffu, s, o);
            if (lane == 0) {
                float v = s + bias[r];
                best = umax64(best, ((ull)ordf(v) << 32) | (ull)(~(unsigned)r));
            }
        }
    }
    if (lane == 0) wbest[wid] = umax64(wbest[wid], best);
    __syncthreads();
    if (tid == 0) {
        ull m = 0;
#pragma unroll
        for (int i = 0; i < 8; i++) m = umax64(m, wbest[i]);
        unsigned id = ~(unsigned)(m & 0xffffffffull);
        sid = (int)id;
        out[t * B_SZ + b] = (float)id;
        g_ccnt[b] = 0;
        g_l1[b] = 0.f;
        g_gmax[b] = 0ull;
    }
    __syncthreads();
    int id = sid;
    for (int k = tid; k < H_SZ; k += 256)
        g_xT[k * 64 + b] = fmaxf(emb[(size_t)id * H_SZ + k], 0.0f);
}

// ---------------- launch ----------------
extern "C" void kernel_launch(void* const* d_in, const int* in_sizes, int n_in,
                              void* d_out, int out_size) {
    const int*   input = (const int*)d_in[0];
    const float* emb   = (const float*)d_in[1];
    const float* eWih  = (const float*)d_in[2];
    const float* eWhh  = (const float*)d_in[3];
    const float* ebih  = (const float*)d_in[4];
    const float* ebhh  = (const float*)d_in[5];
    const float* dWih  = (const float*)d_in[6];
    const float* dWhh  = (const float*)d_in[7];
    const float* dbih  = (const float*)d_in[8];
    const float* dbhh  = (const float*)d_in[9];
    const float* oW    = (const float*)d_in[10];
    const float* ob    = (const float*)d_in[11];
    float* out = (float*)d_out;

    cudaFuncSetAttribute(k_mma, cudaFuncAttributeMaxDynamicSharedMemorySize, DSMEM_SZ);

    k_init<<<76, 256>>>(emb);
    k_prep<<<NT, 256>>>(oW);
    k_gather_enc<<<L_SZ, 256>>>(input, emb);
    k_enc_all<<<ENC_GRID, 512>>>(eWih, eWhh, ebih, ebhh);

    int p = 0;
    for (int t = 0; t < L_SZ; t++) {
        k_gru<<<H_SZ, 512>>>(dWih, dWhh, dbih, dbhh, p, 1 - p);  // h, bf16 h^T, ||h||_1
        k_mma<<<NB_MMA, 128, DSMEM_SZ>>>(ob);                    // approx + global max
        k_select<<<NT, 128>>>();                                 // threshold + candidates
        k_rescore<<<B_SZ, 256>>>(oW, ob, emb, out, t, 1 - p);    // exact argmax + next x
        p = 1 - p;
    }
}

// round 17
// speedup vs baseline: 1.1867x; 1.1867x over previous
#include <cuda_runtime.h>
#include <cuda_bf16.h>
#include <mma.h>
#include <cstdint>
#include <math.h>

#define V_SZ 100000
#define H_SZ 300
#define HP   304
#define B_SZ 64
#define L_SZ 64
#define ENC_GRID 150       // 2 n-rows per block
#define NT   1564          // tiles of 64 rows: 1564*64 = 100096 >= V_SZ
#define KT   304           // MMA K padded: 19 k16-steps
#define CAP  16384
#define AT_BYTES (64 * KT * 2)        // 38912 (A tile, 64 rows)
#define B_BYTES  (B_SZ * KT * 2)      // 38912 (h^T tile)
#define BIAS_OFF (AT_BYTES + B_BYTES) // 77824
#define DSMEM_SZ (BIAS_OFF + 512)     // 78336 -> 2 blocks/SM

typedef unsigned long long ull;
using namespace nvcuda;

// ---------------- device scratch ----------------
__device__ __align__(16) float g_h[2][HP * B_SZ];
__device__ __align__(16) float g_xT[HP * B_SZ];
__device__ __align__(16) float g_xT_all[L_SZ * HP * B_SZ];
__device__ __align__(16) unsigned char g_Wb[(size_t)NT * AT_BYTES];   // bf16 tiles
__device__ __align__(16) unsigned char g_hb[B_BYTES];                 // bf16 h^T
__device__ __align__(16) unsigned char g_approx[(size_t)NT * 64 * B_SZ * 2]; // bf16
__device__ ull g_gmax[B_SZ];
__device__ float g_l1[B_SZ];
__device__ int g_ccnt[B_SZ];
__device__ int g_cand[(size_t)B_SZ * CAP];
__device__ unsigned g_bar;

// ---------------- helpers ----------------
static __device__ __forceinline__ ull pk2(float lo, float hi) {
    ull r; asm("mov.b64 %0, {%1, %2};" : "=l"(r) : "f"(lo), "f"(hi)); return r;
}
static __device__ __forceinline__ void ffma2(ull& d, ull a, ull b) {
    asm("fma.rn.f32x2 %0, %1, %2, %0;" : "+l"(d) : "l"(a), "l"(b));
}
static __device__ __forceinline__ float2 upk2(ull v) {
    float2 r; asm("mov.b64 {%0, %1}, %2;" : "=f"(r.x), "=f"(r.y) : "l"(v)); return r;
}
static __device__ __forceinline__ unsigned ordf(float f) {
    unsigned u = __float_as_uint(f);
    return (u & 0x80000000u) ? ~u : (u | 0x80000000u);
}
static __device__ __forceinline__ float unordf(unsigned u) {
    return __uint_as_float((u & 0x80000000u) ? (u ^ 0x80000000u) : ~u);
}
static __device__ __forceinline__ ull umax64(ull a, ull b) { return a > b ? a : b; }
static __device__ __forceinline__ unsigned s2u(const void* p) {
    return (unsigned)__cvta_generic_to_shared(p);
}
static __device__ __forceinline__ unsigned pbf2(float lo, float hi) {
    unsigned r;
    asm("cvt.rn.bf16x2.f32 %0, %1, %2;" : "=r"(r) : "f"(hi), "f"(lo));
    return r;
}
#define CP16(dst, src) asm volatile("cp.async.cg.shared.global [%0], [%1], 16;" :: "r"(dst), "l"(src))
#define MARGIN_OF(l1) (3.0e-4f * (l1) + 1.5e-3f)

// ---------------- cheap double transcendentals ----------------
static __device__ __forceinline__ double dexp_(double x) {
    const double L2E = 1.4426950408889634074;
    const double LN2HI = 6.93147180369123816490e-01;
    const double LN2LO = 1.90821492927058770002e-10;
    int n = __double2int_rn(x * L2E);
    double nd = (double)n;
    double r = fma(-nd, LN2HI, x);
    r = fma(-nd, LN2LO, r);
    double p = 2.7557319223985893e-6;
    p = fma(p, r, 2.4801587301587302e-5);
    p = fma(p, r, 1.9841269841269841e-4);
    p = fma(p, r, 1.3888888888888889e-3);
    p = fma(p, r, 8.3333333333333333e-3);
    p = fma(p, r, 4.1666666666666667e-2);
    p = fma(p, r, 1.6666666666666667e-1);
    p = fma(p, r, 0.5);
    p = fma(p, r, 1.0);
    p = fma(p, r, 1.0);
    return p * __longlong_as_double((long long)((ull)(1023 + n) << 52));
}
static __device__ __forceinline__ float sigd(float x) {
    double xd = (double)fminf(fmaxf(x, -30.0f), 30.0f);
    double e = dexp_(-xd);
    double den = 1.0 + e;
    double r0 = (double)(1.0f / (float)den);
    r0 = r0 * fma(-den, r0, 2.0);
    return (float)r0;
}
static __device__ __forceinline__ float tanhd(float x) {
    double xd = (double)fminf(fmaxf(x, -30.0f), 30.0f);
    double e = dexp_(-2.0 * xd);
    double den = 1.0 + e;
    double r0 = (double)(1.0f / (float)den);
    r0 = r0 * fma(-den, r0, 2.0);
    return (float)fma(-2.0 * e, r0, 1.0);
}

// ---------------- init ----------------
__global__ void k_init(const float* __restrict__ emb) {
    int i = blockIdx.x * 256 + threadIdx.x;    // 76*256 = HP*64 exact
    int k = i >> 6;
    g_h[0][i] = 0.0f;
    g_h[1][i] = 0.0f;
    g_xT[i] = (k < H_SZ) ? fmaxf(emb[k], 0.0f) : 0.0f;
    if (i == 0) g_bar = 0u;
    if (i < 64) { g_gmax[i] = 0ull; g_l1[i] = 0.f; g_ccnt[i] = 0; }
    if (i < 128) {            // zero g_hb pads (cols 300..303, 64 rows)
        int b = i >> 1, pr = i & 1;
        ((unsigned*)g_hb)[(b * KT + 300) / 2 + pr] = 0u;
    }
}

// ---------------- prep: W -> bf16 row-major tiles [64][KT] ---------------
__global__ __launch_bounds__(256) void k_prep(const float* __restrict__ W) {
    int blk = blockIdx.x, tid = threadIdx.x;
    unsigned* dst = (unsigned*)(g_Wb + (size_t)blk * AT_BYTES);
    for (int i = tid; i < 64 * (KT / 2); i += 256) {
        int l = i / (KT / 2), kw = i - l * (KT / 2);
        int k0 = kw * 2;
        int row = blk * 64 + l;
        float v0 = 0.f, v1 = 0.f;
        if (row < V_SZ) {
            if (k0 < H_SZ)     v0 = W[(size_t)row * H_SZ + k0];
            if (k0 + 1 < H_SZ) v1 = W[(size_t)row * H_SZ + k0 + 1];
        }
        dst[i] = pbf2(v0, v1);
    }
}

// ---------------- gather encoder embeddings ----------------
__global__ void k_gather_enc(const int* __restrict__ input, const float* __restrict__ emb) {
    __shared__ int ids[B_SZ];
    int t = blockIdx.x, tid = threadIdx.x;
    if (tid < B_SZ) ids[tid] = input[t * B_SZ + tid];
    __syncthreads();
    for (int i = tid; i < B_SZ * H_SZ; i += 256) {
        int b = i / H_SZ, k = i - b * H_SZ;
        g_xT_all[((size_t)t * HP + k) * B_SZ + b] = emb[(size_t)ids[b] * H_SZ + k];
    }
    g_xT_all[((size_t)t * HP + H_SZ) * B_SZ + tid] = 0.0f;
}

// ---------------- encoder: persistent, grid 150 (2 n-rows/block) ---------
__global__ __launch_bounds__(512, 2) void k_enc_all(
    const float* __restrict__ W_ih, const float* __restrict__ W_hh,
    const float* __restrict__ b_ih, const float* __restrict__ b_hh)
{
    __shared__ __align__(16) float Ws[12][HP];       // 14592 B, persists
    __shared__ __align__(16) ull Red[8 * 12 * 32];   // 24576 B

    int tid = threadIdx.x;
    int n0 = blockIdx.x * 2;
    int w = tid >> 5, lane = tid & 31;

    for (int i = tid; i < 12 * 75; i += 512) {
        int row = i / 75, q = i - row * 75;
        const float* src;
        if (row < 6) src = W_ih + (size_t)((row >> 1) * H_SZ + n0 + (row & 1)) * H_SZ;
        else { int rr = row - 6; src = W_hh + (size_t)((rr >> 1) * H_SZ + n0 + (rr & 1)) * H_SZ; }
        *(float4*)&Ws[row][q * 4] = *(const float4*)(src + q * 4);
    }
    if (tid < 12) { float4 z = {0.f, 0.f, 0.f, 0.f}; *(float4*)&Ws[tid][300] = z; }

    float bi_r = 0, bi_z = 0, bi_n = 0, bh_r = 0, bh_z = 0, bh_n = 0;
    int nl = 0, bb = 0, nn_i = 0;
    if (tid < 128) {
        nl = tid >> 6; bb = tid & 63; nn_i = n0 + nl;
        bi_r = b_ih[nn_i]; bi_z = b_ih[H_SZ + nn_i]; bi_n = b_ih[2 * H_SZ + nn_i];
        bh_r = b_hh[nn_i]; bh_z = b_hh[H_SZ + nn_i]; bh_n = b_hh[2 * H_SZ + nn_i];
    }
    __syncthreads();

    int ks = w * 19;
    for (int t = 0; t < L_SZ; t++) {
        const float* xp = g_xT_all + (size_t)t * HP * B_SZ;
        const float* hp = g_h[t & 1];
        float* ho = g_h[(t + 1) & 1];

        ull a[12];
#pragma unroll
        for (int r = 0; r < 12; r++) a[r] = 0ull;

#pragma unroll 4
        for (int k = ks; k < ks + 19; k++) {
            ull xq = *(const ull*)(xp + k * 64 + lane * 2);
            ull hq = *(const ull*)(hp + k * 64 + lane * 2);
#pragma unroll
            for (int r = 0; r < 6; r++) ffma2(a[r], pk2(Ws[r][k], Ws[r][k]), xq);
#pragma unroll
            for (int r = 6; r < 12; r++) ffma2(a[r], pk2(Ws[r][k], Ws[r][k]), hq);
        }

        if (w >= 8) {
#pragma unroll
            for (int r = 0; r < 12; r++) Red[((w - 8) * 12 + r) * 32 + lane] = a[r];
        }
        __syncthreads();
        if (w < 8) {
#pragma unroll
            for (int r = 0; r < 12; r++) {
                ull o = Red[(w * 12 + r) * 32 + lane];
                float2 pa = upk2(a[r]), po = upk2(o);
                Red[(w * 12 + r) * 32 + lane] = pk2(pa.x + po.x, pa.y + po.y);
            }
        }
        __syncthreads();
        if (tid < 128) {
            const float* Rf = (const float*)Red;   // [8][12][64]
            float sir = 0, siz = 0, sin_ = 0, shr = 0, shz = 0, shn = 0;
#pragma unroll
            for (int p2 = 0; p2 < 8; p2++) {
                const float* base = Rf + p2 * 768;
                sir  += base[(0 + nl) * 64 + bb];
                siz  += base[(2 + nl) * 64 + bb];
                sin_ += base[(4 + nl) * 64 + bb];
                shr  += base[(6 + nl) * 64 + bb];
                shz  += base[(8 + nl) * 64 + bb];
                shn  += base[(10 + nl) * 64 + bb];
            }
            float r = sigd(sir + bi_r + shr + bh_r);
            float z = sigd(siz + bi_z + shz + bh_z);
            float nn = tanhd(sin_ + bi_n + r * (shn + bh_n));
            float hold = hp[nn_i * 64 + bb];
            ho[nn_i * 64 + bb] = (1.0f - z) * nn + z * hold;
            __threadfence();
        }
        __syncthreads();
        if (tid == 0) {
            atomicAdd(&g_bar, 1u);
            unsigned target = (unsigned)(t + 1) * (unsigned)ENC_GRID;
            unsigned v;
            do {
                asm volatile("ld.acquire.gpu.u32 %0, [%1];" : "=r"(v) : "l"(&g_bar));
            } while (v < target);
        }
        __syncthreads();
    }
}

// ---------------- decoder GRU: grid 300 (1 n/block), block 512 -----------
__global__ __launch_bounds__(512) void k_gru(
    const float* __restrict__ W_ih, const float* __restrict__ W_hh,
    const float* __restrict__ b_ih, const float* __restrict__ b_hh,
    int hin, int hout)
{
    __shared__ __align__(16) char smraw[12288];
    float (*Ws)[HP] = (float(*)[HP])smraw;    // [6][304] during main loop
    ull* Red = (ull*)smraw;                   // [8][6][32] after (union)

    int tid = threadIdx.x;
    int n = blockIdx.x;
    int w = tid >> 5, lane = tid & 31;

    for (int i = tid; i < 6 * 75; i += 512) {
        int row = i / 75, q = i - row * 75;
        const float* src = ((row < 3) ? W_ih + (size_t)(row * H_SZ + n) * H_SZ
                                      : W_hh + (size_t)((row - 3) * H_SZ + n) * H_SZ);
        *(float4*)&Ws[row][q * 4] = *(const float4*)(src + q * 4);
    }
    if (tid < 6) { float4 z = {0.f, 0.f, 0.f, 0.f}; *(float4*)&Ws[tid][300] = z; }
    __syncthreads();

    const float* xp = g_xT;
    const float* hp = g_h[hin];
    int ks = w * 19;

    ull a[6];
#pragma unroll
    for (int r = 0; r < 6; r++) a[r] = 0ull;

#pragma unroll 4
    for (int k = ks; k < ks + 19; k++) {
        ull xq = *(const ull*)(xp + k * 64 + lane * 2);
        ull hq = *(const ull*)(hp + k * 64 + lane * 2);
#pragma unroll
        for (int r = 0; r < 3; r++) ffma2(a[r], pk2(Ws[r][k], Ws[r][k]), xq);
#pragma unroll
        for (int r = 3; r < 6; r++) ffma2(a[r], pk2(Ws[r][k], Ws[r][k]), hq);
    }
    __syncthreads();

    if (w >= 8) {
#pragma unroll
        for (int r = 0; r < 6; r++) Red[((w - 8) * 6 + r) * 32 + lane] = a[r];
    }
    __syncthreads();
    if (w < 8) {
#pragma unroll
        for (int r = 0; r < 6; r++) {
            ull o = Red[(w * 6 + r) * 32 + lane];
            float2 pa = upk2(a[r]), po = upk2(o);
            Red[(w * 6 + r) * 32 + lane] = pk2(pa.x + po.x, pa.y + po.y);
        }
    }
    __syncthreads();

    if (tid < 64) {
        int b = tid;
        const float* Rf = (const float*)Red;    // [8][6][64]
        float sir = 0, siz = 0, sin_ = 0, shr = 0, shz = 0, shn = 0;
#pragma unroll
        for (int p2 = 0; p2 < 8; p2++) {
            const float* base = Rf + p2 * 384;
            sir  += base[b];
            siz  += base[64 + b];
            sin_ += base[128 + b];
            shr  += base[192 + b];
            shz  += base[256 + b];
            shn  += base[320 + b];
        }
        float r = sigd(sir + b_ih[n] + shr + b_hh[n]);
        float z = sigd(siz + b_ih[H_SZ + n] + shz + b_hh[H_SZ + n]);
        float nn = tanhd(sin_ + b_ih[2 * H_SZ + n] + r * (shn + b_hh[2 * H_SZ + n]));
        float hold = hp[n * 64 + b];
        float hv = (1.0f - z) * nn + z * hold;
        g_h[hout][n * 64 + b] = hv;
        ((__nv_bfloat16*)g_hb)[b * KT + n] = __float2bfloat16(hv);
        atomicAdd(&g_l1[b], fabsf(hv));
    }
}

// ---------------- logits: WMMA bf16, 64-row tiles, 2 blocks/SM -----------
__global__ __launch_bounds__(128) void k_mma(const float* __restrict__ bias) {
    extern __shared__ __align__(16) char smx[];
    int tid = threadIdx.x, blk = blockIdx.x;
    int w = tid >> 5;

    const unsigned char* srcA = g_Wb + (size_t)blk * AT_BYTES;
    unsigned smA = s2u(smx), smB = smA + AT_BYTES;
    for (int i = tid; i < AT_BYTES / 16; i += 128) CP16(smA + i * 16, srcA + i * 16);
    for (int i = tid; i < B_BYTES / 16; i += 128) CP16(smB + i * 16, g_hb + i * 16);
    if (tid < 64) {
        int row = blk * 64 + tid;
        ((float*)(smx + BIAS_OFF))[tid] = (row < V_SZ) ? bias[row] : 0.f;
    }
    asm volatile("cp.async.commit_group;");
    asm volatile("cp.async.wait_group 0;");
    __syncthreads();

    const __nv_bfloat16* Af = (const __nv_bfloat16*)smx;
    const __nv_bfloat16* Bf = (const __nv_bfloat16*)(smx + AT_BYTES);

    wmma::fragment<wmma::accumulator, 16, 16, 16, float> cfr[4];
#pragma unroll
    for (int ni = 0; ni < 4; ni++) wmma::fill_fragment(cfr[ni], 0.0f);

    for (int ks = 0; ks < KT / 16; ks++) {     // 19 k-steps
        wmma::fragment<wmma::matrix_a, 16, 16, 16, __nv_bfloat16, wmma::row_major> af;
        wmma::load_matrix_sync(af, Af + (w * 16) * KT + ks * 16, KT);
#pragma unroll
        for (int ni = 0; ni < 4; ni++) {
            wmma::fragment<wmma::matrix_b, 16, 16, 16, __nv_bfloat16, wmma::col_major> bf;
            wmma::load_matrix_sync(bf, Bf + (ni * 16) * KT + ks * 16, KT);
            wmma::mma_sync(cfr[ni], af, bf, cfr[ni]);
        }
    }
    __syncthreads();

    float* sap = (float*)smx;                  // [64][64] f32 overlay on A region
#pragma unroll
    for (int ni = 0; ni < 4; ni++)
        wmma::store_matrix_sync(sap + (w * 16) * 64 + ni * 16, cfr[ni], 64,
                                wmma::mem_row_major);
    __syncthreads();

    const float* sb = (const float*)(smx + BIAS_OFF);
    unsigned* gdst = (unsigned*)(g_approx + (size_t)blk * 64 * B_SZ * 2);
#pragma unroll
    for (int j = 0; j < 16; j++) {
        int p = j * 128 + tid;                 // 2048 bf16x2 pairs
        int r = p >> 5, bq = p & 31;
        float bb = sb[r];
        bool ok = (blk * 64 + r) < V_SZ;
        float v0 = ok ? (sap[r * 64 + bq * 2] + bb) : -1e30f;
        float v1 = ok ? (sap[r * 64 + bq * 2 + 1] + bb) : -1e30f;
        sap[r * 64 + bq * 2] = v0;
        sap[r * 64 + bq * 2 + 1] = v1;
        unsigned lo = (unsigned)__bfloat16_as_ushort(__float2bfloat16_ru(v0));
        unsigned hi = (unsigned)__bfloat16_as_ushort(__float2bfloat16_ru(v1));
        gdst[p] = lo | (hi << 16);
    }
    __syncthreads();

    if (tid < 64) {
        ull m = 0;
        for (int r = 0; r < 64; r++) {
            float v = sap[r * 64 + tid];
            m = umax64(m, ((ull)ordf(v) << 32) | (ull)(~(unsigned)(blk * 64 + r)));
        }
        atomicMax(&g_gmax[tid], m);            // RED.MAX (result unused)
    }
}

// ---------------- select candidates (thr computed locally) ---------------
__global__ __launch_bounds__(128) void k_select() {
    __shared__ float sthr[64];
    int tid = threadIdx.x, blk = blockIdx.x;
    if (tid < 64)
        sthr[tid] = unordf((unsigned)(g_gmax[tid] >> 32)) - MARGIN_OF(g_l1[tid]);
    __syncthreads();
    const unsigned* ap = (const unsigned*)(g_approx + (size_t)blk * 64 * B_SZ * 2);
    int base_row = blk * 64;
#pragma unroll 4
    for (int j = 0; j < 16; j++) {
        int p = j * 128 + tid;                 // pair: row r, batches 2bq, 2bq+1
        unsigned pv = ap[p];
        int r = p >> 5, bq = p & 31;
        float v0 = __bfloat162float(__ushort_as_bfloat16((unsigned short)(pv & 0xffffu)));
        float v1 = __bfloat162float(__ushort_as_bfloat16((unsigned short)(pv >> 16)));
        int c0 = bq * 2, c1 = bq * 2 + 1;
        if (v0 >= sthr[c0]) {
            int pos = atomicAdd(&g_ccnt[c0], 1);
            if (pos < CAP) g_cand[(size_t)c0 * CAP + pos] = base_row + r;
        }
        if (v1 >= sthr[c1]) {
            int pos = atomicAdd(&g_ccnt[c1], 1);
            if (pos < CAP) g_cand[(size_t)c1 * CAP + pos] = base_row + r;
        }
    }
}

// ---------------- rescore exact + finalize (overflow-safe) ---------------
__global__ __launch_bounds__(256) void k_rescore(
    const float* __restrict__ W, const float* __restrict__ bias,
    const float* __restrict__ emb, float* __restrict__ out, int t, int hin)
{
    __shared__ float hsh[H_SZ];
    __shared__ ull wbest[8];
    __shared__ int sid;
    int b = blockIdx.x, tid = threadIdx.x, wid = tid >> 5, lane = tid & 31;
    for (int k = tid; k < H_SZ; k += 256) hsh[k] = g_h[hin][k * 64 + b];
    if (tid < 8) wbest[tid] = 0ull;
    __syncthreads();
    int n = g_ccnt[b];
    ull best = 0;
    if (n <= CAP) {
        for (int ci = wid; ci < n; ci += 8) {
            int r = g_cand[(size_t)b * CAP + ci];
            const float* wr = W + (size_t)r * H_SZ;
            float s = 0.f;
            for (int k = lane; k < H_SZ; k += 32) s = fmaf(wr[k], hsh[k], s);
#pragma unroll
            for (int o = 16; o; o >>= 1) s += __shfl_xor_sync(0xffffffffu, s, o);
            if (lane == 0) {
                float v = s + bias[r];
                best = umax64(best, ((ull)ordf(v) << 32) | (ull)(~(unsigned)r));
            }
        }
    } else {
        for (int r = wid; r < V_SZ; r += 8) {
            const float* wr = W + (size_t)r * H_SZ;
            float s = 0.f;
            for (int k = lane; k < H_SZ; k += 32) s = fmaf(wr[k], hsh[k], s);
#pragma unroll
            for (int o = 16; o; o >>= 1) s += __shfl_xor_sync(0xffffffffu, s, o);
            if (lane == 0) {
                float v = s + bias[r];
                best = umax64(best, ((ull)ordf(v) << 32) | (ull)(~(unsigned)r));
            }
        }
    }
    if (lane == 0) wbest[wid] = umax64(wbest[wid], best);
    __syncthreads();
    if (tid == 0) {
        ull m = 0;
#pragma unroll
        for (int i = 0; i < 8; i++) m = umax64(m, wbest[i]);
        unsigned id = ~(unsigned)(m & 0xffffffffull);
        sid = (int)id;
        out[t * B_SZ + b] = (float)id;
        g_ccnt[b] = 0;
        g_l1[b] = 0.f;
        g_gmax[b] = 0ull;
    }
    __syncthreads();
    int id = sid;
    for (int k = tid; k < H_SZ; k += 256)
        g_xT[k * 64 + b] = fmaxf(emb[(size_t)id * H_SZ + k], 0.0f);
}

// ---------------- launch ----------------
extern "C" void kernel_launch(void* const* d_in, const int* in_sizes, int n_in,
                              void* d_out, int out_size) {
    const int*   input = (const int*)d_in[0];
    const float* emb   = (const float*)d_in[1];
    const float* eWih  = (const float*)d_in[2];
    const float* eWhh  = (const float*)d_in[3];
    const float* ebih  = (const float*)d_in[4];
    const float* ebhh  = (const float*)d_in[5];
    const float* dWih  = (const float*)d_in[6];
    const float* dWhh  = (const float*)d_in[7];
    const float* dbih  = (const float*)d_in[8];
    const float* dbhh  = (const float*)d_in[9];
    const float* oW    = (const float*)d_in[10];
    const float* ob    = (const float*)d_in[11];
    float* out = (float*)d_out;

    cudaFuncSetAttribute(k_mma, cudaFuncAttributeMaxDynamicSharedMemorySize, DSMEM_SZ);

    k_init<<<76, 256>>>(emb);
    k_prep<<<NT, 256>>>(oW);
    k_gather_enc<<<L_SZ, 256>>>(input, emb);
    k_enc_all<<<ENC_GRID, 512>>>(eWih, eWhh, ebih, ebhh);

    int p = 0;
    for (int t = 0; t < L_SZ; t++) {
        k_gru<<<H_SZ, 512>>>(dWih, dWhh, dbih, dbhh, p, 1 - p);  // h, bf16 h^T, ||h||_1
        k_mma<<<NT, 128, DSMEM_SZ>>>(ob);                        // approx + global max
        k_select<<<NT, 128>>>();                                 // threshold + candidates
        k_rescore<<<B_SZ, 256>>>(oW, ob, emb, out, t, 1 - p);    // exact argmax + next x
        p = 1 - p;
    }
}